// round 2
// baseline (speedup 1.0000x reference)
#include <cuda_runtime.h>
#include <math.h>

// Problem constants
#define BB_    4
#define TT_    4096
#define EE_    1024
#define DFF_   4096
#define CH_    64
#define ST_    32
#define NCHUNK 128
#define ROWS_  (BB_ * CH_)   // 256

// ---------------- device scratch (no allocations allowed) ----------------
__device__ float g_M[CH_ * CH_];           // 64x64 combined temporal mix
__device__ float g_proc[ROWS_ * EE_];      // carry: proc of previous step
__device__ float g_cn[ROWS_ * EE_];        // LN1 output
__device__ float g_res2[ROWS_ * EE_];      // fft + residual
__device__ float g_cn2[ROWS_ * EE_];       // LN2 output
__device__ float g_f[ROWS_ * DFF_];        // sin(gate)*val
__device__ float g_part[2 * ROWS_ * EE_];  // split-K partials for down GEMM

// ---------------- M = w_fft2 @ w_fft1 (64x48 @ 48x64 contraction) --------
__global__ void k_precompute_M(const float* __restrict__ w1,
                               const float* __restrict__ w2) {
    int idx = blockIdx.x * blockDim.x + threadIdx.x; // 0..4095
    int t = idx >> 6, s = idx & 63;
    float acc = 0.f;
    #pragma unroll
    for (int u = 0; u < 48; u++)
        acc += w2[t * 48 + u] * w1[u * 64 + s];
    g_M[idx] = acc;
}

// prime carry: g_proc rows 32..63 of each batch = x[:, 0:32, :]
__global__ void k_init(const float* __restrict__ x) {
    int idx = blockIdx.x * blockDim.x + threadIdx.x; // 0 .. 4*32*1024-1
    int b = idx >> 15;
    int rem = idx & 32767;
    int t = rem >> 10;
    int e = rem & 1023;
    g_proc[(b * CH_ + ST_ + t) * EE_ + e] = x[((long)b * TT_ + t) * EE_ + e];
}

// ---------------- LN1 over mixed rows ------------------------------------
// mixed row t: t<32 -> g_proc[b, 32+t]; t>=32 -> x[b, step*32+t] (0 past T)
__global__ __launch_bounds__(256) void k_ln1(const float* __restrict__ x,
                                             const float* __restrict__ w,
                                             const float* __restrict__ bia,
                                             int step) {
    int row = blockIdx.x;            // b*64 + t
    int bb = row >> 6, t = row & 63;
    int tid = threadIdx.x;
    float4 v;
    if (t < ST_) {
        v = *(const float4*)&g_proc[(bb * CH_ + ST_ + t) * EE_ + 4 * tid];
    } else {
        int gt = step * ST_ + t;
        if (gt < TT_)
            v = *(const float4*)&x[((long)bb * TT_ + gt) * EE_ + 4 * tid];
        else
            v = make_float4(0.f, 0.f, 0.f, 0.f);
    }
    float s  = v.x + v.y + v.z + v.w;
    float s2 = v.x * v.x + v.y * v.y + v.z * v.z + v.w * v.w;
    __shared__ float ws[8], ws2[8];
    #pragma unroll
    for (int o = 16; o > 0; o >>= 1) {
        s  += __shfl_xor_sync(0xffffffffu, s, o);
        s2 += __shfl_xor_sync(0xffffffffu, s2, o);
    }
    int warp = tid >> 5, lane = tid & 31;
    if (lane == 0) { ws[warp] = s; ws2[warp] = s2; }
    __syncthreads();
    if (tid < 32) {
        s  = (lane < 8) ? ws[lane]  : 0.f;
        s2 = (lane < 8) ? ws2[lane] : 0.f;
        #pragma unroll
        for (int o = 4; o > 0; o >>= 1) {
            s  += __shfl_xor_sync(0xffffffffu, s, o);
            s2 += __shfl_xor_sync(0xffffffffu, s2, o);
        }
        if (lane == 0) { ws[0] = s; ws2[0] = s2; }
    }
    __syncthreads();
    float mu  = ws[0] * (1.f / EE_);
    float var = ws2[0] * (1.f / EE_) - mu * mu;
    float rs  = rsqrtf(var + 1e-5f);
    float4 wv = *(const float4*)&w[4 * tid];
    float4 bv = *(const float4*)&bia[4 * tid];
    float4 o;
    o.x = (v.x - mu) * rs * wv.x + bv.x;
    o.y = (v.y - mu) * rs * wv.y + bv.y;
    o.z = (v.z - mu) * rs * wv.z + bv.z;
    o.w = (v.w - mu) * rs * wv.w + bv.w;
    *(float4*)&g_cn[row * EE_ + 4 * tid] = o;
}

// ---------------- temporal mix + residual: res2 = M*cn + x_chunk ---------
// grid (4 batches, 4 e-groups of 256, 4 t-groups of 16), 256 threads
__global__ __launch_bounds__(256) void k_fft(const float* __restrict__ x,
                                             int step) {
    int bb = blockIdx.x;
    int e  = blockIdx.y * 256 + threadIdx.x;
    int t0 = blockIdx.z * 16;
    __shared__ float Ms[16][64];
    for (int l = threadIdx.x; l < 16 * 64; l += 256)
        Ms[l >> 6][l & 63] = g_M[(t0 + (l >> 6)) * 64 + (l & 63)];
    __syncthreads();
    float col[64];
    #pragma unroll
    for (int s_ = 0; s_ < 64; s_++)
        col[s_] = g_cn[(bb * CH_ + s_) * EE_ + e];
    for (int tl = 0; tl < 16; tl++) {
        float acc = 0.f;
        #pragma unroll
        for (int s4 = 0; s4 < 16; s4++) {
            float4 m = *(const float4*)&Ms[tl][s4 * 4];
            acc += m.x * col[4 * s4 + 0];
            acc += m.y * col[4 * s4 + 1];
            acc += m.z * col[4 * s4 + 2];
            acc += m.w * col[4 * s4 + 3];
        }
        int t = t0 + tl;
        int gt = step * ST_ + t;
        float resid = (gt < TT_) ? x[((long)bb * TT_ + gt) * EE_ + e] : 0.f;
        g_res2[(bb * CH_ + t) * EE_ + e] = acc + resid;
    }
}

// ---------------- LN2 over res2 ------------------------------------------
__global__ __launch_bounds__(256) void k_ln2(const float* __restrict__ w,
                                             const float* __restrict__ bia) {
    int row = blockIdx.x;
    int tid = threadIdx.x;
    float4 v = *(const float4*)&g_res2[row * EE_ + 4 * tid];
    float s  = v.x + v.y + v.z + v.w;
    float s2 = v.x * v.x + v.y * v.y + v.z * v.z + v.w * v.w;
    __shared__ float ws[8], ws2[8];
    #pragma unroll
    for (int o = 16; o > 0; o >>= 1) {
        s  += __shfl_xor_sync(0xffffffffu, s, o);
        s2 += __shfl_xor_sync(0xffffffffu, s2, o);
    }
    int warp = tid >> 5, lane = tid & 31;
    if (lane == 0) { ws[warp] = s; ws2[warp] = s2; }
    __syncthreads();
    if (tid < 32) {
        s  = (lane < 8) ? ws[lane]  : 0.f;
        s2 = (lane < 8) ? ws2[lane] : 0.f;
        #pragma unroll
        for (int o = 4; o > 0; o >>= 1) {
            s  += __shfl_xor_sync(0xffffffffu, s, o);
            s2 += __shfl_xor_sync(0xffffffffu, s2, o);
        }
        if (lane == 0) { ws[0] = s; ws2[0] = s2; }
    }
    __syncthreads();
    float mu  = ws[0] * (1.f / EE_);
    float var = ws2[0] * (1.f / EE_) - mu * mu;
    float rs  = rsqrtf(var + 1e-5f);
    float4 wv = *(const float4*)&w[4 * tid];
    float4 bv = *(const float4*)&bia[4 * tid];
    float4 o;
    o.x = (v.x - mu) * rs * wv.x + bv.x;
    o.y = (v.y - mu) * rs * wv.y + bv.y;
    o.z = (v.z - mu) * rs * wv.z + bv.z;
    o.w = (v.w - mu) * rs * wv.w + bv.w;
    *(float4*)&g_cn2[row * EE_ + 4 * tid] = o;
}

// ---------------- up GEMM + sin gate -------------------------------------
// C tiles: 64 rows x (64 gate + 64 val), K=1024, BK=16. 128 threads, 8x(4+4).
__global__ __launch_bounds__(128) void k_mlp_up(const float* __restrict__ w_up,
                                                const float* __restrict__ b_up) {
    __shared__ float As [16][64];
    __shared__ float Bgs[16][64];
    __shared__ float Bvs[16][64];
    int m0 = blockIdx.x * 64;
    int n0 = blockIdx.y * 64;
    int tid = threadIdx.x;
    int ty = tid >> 4, tx = tid & 15;
    float accg[8][4] = {};
    float accv[8][4] = {};
    for (int k0 = 0; k0 < EE_; k0 += 16) {
        __syncthreads();
        #pragma unroll
        for (int l = tid; l < 256; l += 128) {
            int r = l >> 2, kc = (l & 3) * 4;
            float4 v = *(const float4*)&g_cn2[(m0 + r) * EE_ + k0 + kc];
            As[kc + 0][r] = v.x; As[kc + 1][r] = v.y;
            As[kc + 2][r] = v.z; As[kc + 3][r] = v.w;
        }
        #pragma unroll
        for (int l = tid; l < 256; l += 128) {
            int r = l >> 2, kc = (l & 3) * 4;
            float4 g = *(const float4*)&w_up[(long)(n0 + r) * EE_ + k0 + kc];
            float4 v = *(const float4*)&w_up[(long)(DFF_ + n0 + r) * EE_ + k0 + kc];
            Bgs[kc + 0][r] = g.x; Bgs[kc + 1][r] = g.y;
            Bgs[kc + 2][r] = g.z; Bgs[kc + 3][r] = g.w;
            Bvs[kc + 0][r] = v.x; Bvs[kc + 1][r] = v.y;
            Bvs[kc + 2][r] = v.z; Bvs[kc + 3][r] = v.w;
        }
        __syncthreads();
        #pragma unroll
        for (int k = 0; k < 16; k++) {
            float4 a0 = *(const float4*)&As[k][ty * 8];
            float4 a1 = *(const float4*)&As[k][ty * 8 + 4];
            float4 bg = *(const float4*)&Bgs[k][tx * 4];
            float4 bv = *(const float4*)&Bvs[k][tx * 4];
            float a[8] = {a0.x, a0.y, a0.z, a0.w, a1.x, a1.y, a1.z, a1.w};
            float gA[4] = {bg.x, bg.y, bg.z, bg.w};
            float vA[4] = {bv.x, bv.y, bv.z, bv.w};
            #pragma unroll
            for (int i = 0; i < 8; i++)
                #pragma unroll
                for (int j = 0; j < 4; j++) {
                    accg[i][j] += a[i] * gA[j];
                    accv[i][j] += a[i] * vA[j];
                }
        }
    }
    float4 bug = *(const float4*)&b_up[n0 + tx * 4];
    float4 buv = *(const float4*)&b_up[DFF_ + n0 + tx * 4];
    float bg_[4] = {bug.x, bug.y, bug.z, bug.w};
    float bv_[4] = {buv.x, buv.y, buv.z, buv.w};
    #pragma unroll
    for (int i = 0; i < 8; i++) {
        int row = m0 + ty * 8 + i;
        float o[4];
        #pragma unroll
        for (int j = 0; j < 4; j++)
            o[j] = __sinf(accg[i][j] + bg_[j]) * (accv[i][j] + bv_[j]);
        float4 ov = make_float4(o[0], o[1], o[2], o[3]);
        *(float4*)&g_f[row * DFF_ + n0 + tx * 4] = ov;
    }
}

// ---------------- down GEMM, split-K=2, writes partials ------------------
// grid (4 Mtiles, 16 Ntiles, 2 Ksplits), 128 threads, 8x4 per thread
__global__ __launch_bounds__(128) void k_mlp_down(const float* __restrict__ w_down) {
    __shared__ float As[16][64];
    __shared__ float Bs[16][64];
    int m0 = blockIdx.x * 64;
    int n0 = blockIdx.y * 64;
    int kb = blockIdx.z * (DFF_ / 2);
    int tid = threadIdx.x;
    int ty = tid >> 4, tx = tid & 15;
    float acc[8][4] = {};
    for (int k0 = kb; k0 < kb + DFF_ / 2; k0 += 16) {
        __syncthreads();
        #pragma unroll
        for (int l = tid; l < 256; l += 128) {
            int r = l >> 2, kc = (l & 3) * 4;
            float4 v = *(const float4*)&g_f[(m0 + r) * DFF_ + k0 + kc];
            As[kc + 0][r] = v.x; As[kc + 1][r] = v.y;
            As[kc + 2][r] = v.z; As[kc + 3][r] = v.w;
        }
        #pragma unroll
        for (int l = tid; l < 256; l += 128) {
            int r = l >> 2, kc = (l & 3) * 4;
            float4 v = *(const float4*)&w_down[(long)(n0 + r) * DFF_ + k0 + kc];
            Bs[kc + 0][r] = v.x; Bs[kc + 1][r] = v.y;
            Bs[kc + 2][r] = v.z; Bs[kc + 3][r] = v.w;
        }
        __syncthreads();
        #pragma unroll
        for (int k = 0; k < 16; k++) {
            float4 a0 = *(const float4*)&As[k][ty * 8];
            float4 a1 = *(const float4*)&As[k][ty * 8 + 4];
            float4 b  = *(const float4*)&Bs[k][tx * 4];
            float a[8] = {a0.x, a0.y, a0.z, a0.w, a1.x, a1.y, a1.z, a1.w};
            float bA[4] = {b.x, b.y, b.z, b.w};
            #pragma unroll
            for (int i = 0; i < 8; i++)
                #pragma unroll
                for (int j = 0; j < 4; j++)
                    acc[i][j] += a[i] * bA[j];
        }
    }
    float* dst = &g_part[blockIdx.z * (ROWS_ * EE_)];
    #pragma unroll
    for (int i = 0; i < 8; i++) {
        int row = m0 + ty * 8 + i;
        float4 ov = make_float4(acc[i][0], acc[i][1], acc[i][2], acc[i][3]);
        *(float4*)&dst[row * EE_ + n0 + tx * 4] = ov;
    }
}

// ---------------- epilogue: combine partials + bias + res2 ---------------
__global__ __launch_bounds__(256) void k_epilogue(const float* __restrict__ b_down,
                                                  float* __restrict__ out,
                                                  int step) {
    int row = blockIdx.x;
    int bb = row >> 6, t = row & 63;
    int e = threadIdx.x * 4;
    float4 p0 = *(const float4*)&g_part[row * EE_ + e];
    float4 p1 = *(const float4*)&g_part[ROWS_ * EE_ + row * EE_ + e];
    float4 r2 = *(const float4*)&g_res2[row * EE_ + e];
    float4 bd = *(const float4*)&b_down[e];
    float4 v;
    v.x = p0.x + p1.x + r2.x + bd.x;
    v.y = p0.y + p1.y + r2.y + bd.y;
    v.z = p0.z + p1.z + r2.z + bd.z;
    v.w = p0.w + p1.w + r2.w + bd.w;
    *(float4*)&g_proc[row * EE_ + e] = v;
    if (t < ST_)
        *(float4*)&out[((long)bb * TT_ + step * ST_ + t) * EE_ + e] = v;
}

// ---------------- launch ---------------------------------------------------
extern "C" void kernel_launch(void* const* d_in, const int* in_sizes, int n_in,
                              void* d_out, int out_size) {
    (void)in_sizes; (void)n_in; (void)out_size;
    const float* x      = (const float*)d_in[0];
    const float* ln1_w  = (const float*)d_in[1];
    const float* ln1_b  = (const float*)d_in[2];
    const float* w_fft1 = (const float*)d_in[3];
    const float* w_fft2 = (const float*)d_in[4];
    const float* ln2_w  = (const float*)d_in[5];
    const float* ln2_b  = (const float*)d_in[6];
    const float* w_up   = (const float*)d_in[7];
    const float* b_up   = (const float*)d_in[8];
    const float* w_down = (const float*)d_in[9];
    const float* b_down = (const float*)d_in[10];
    float* out = (float*)d_out;

    k_precompute_M<<<16, 256>>>(w_fft1, w_fft2);
    k_init<<<512, 256>>>(x);

    for (int i = 0; i < NCHUNK; i++) {
        k_ln1<<<ROWS_, 256>>>(x, ln1_w, ln1_b, i);
        k_fft<<<dim3(BB_, 4, 4), 256>>>(x, i);
        k_ln2<<<ROWS_, 256>>>(ln2_w, ln2_b);
        k_mlp_up<<<dim3(4, 64), 128>>>(w_up, b_up);
        k_mlp_down<<<dim3(4, 16, 2), 128>>>(w_down);
        k_epilogue<<<ROWS_, 256>>>(b_down, out, i);
    }
}

// round 4
// speedup vs baseline: 3.2625x; 3.2625x over previous
#include <cuda_runtime.h>
#include <cuda_bf16.h>
#include <math.h>
#include <stdint.h>

// Problem constants
#define BB_    4
#define TT_    4096
#define EE_    1024
#define DFF_   4096
#define CH_    64
#define ST_    32
#define NCHUNK 128
#define ROWS_  (BB_ * CH_)   // 256

// GEMM smem layout: 4 arrays (Ah, Al, Bh, Bl), 128 rows x 64 k, bf16,
// row stride padded to 144B (conflict-free ldmatrix), double buffered.
#define RS_     144
#define ABUF_   (128 * RS_)          // 18432
#define BUFSZ_  (4 * ABUF_)          // 73728
#define GSMEM_  (2 * BUFSZ_)         // 147456

// ================= helpers =================
__device__ __forceinline__ uint32_t smem_u32(const void* p) {
    uint32_t a;
    asm("{ .reg .u64 t; cvta.to.shared.u64 t, %1; cvt.u32.u64 %0, t; }"
        : "=r"(a) : "l"(p));
    return a;
}
__device__ __forceinline__ void cp16(uint32_t d, const void* s) {
    asm volatile("cp.async.cg.shared.global [%0], [%1], 16;" :: "r"(d), "l"(s) : "memory");
}
#define CP_COMMIT() asm volatile("cp.async.commit_group;" ::: "memory")
#define CP_WAIT0()  asm volatile("cp.async.wait_group 0;" ::: "memory")
#define CP_WAIT1()  asm volatile("cp.async.wait_group 1;" ::: "memory")

__device__ __forceinline__ void ldmx4(uint32_t* r, uint32_t addr) {
    asm volatile("ldmatrix.sync.aligned.m8n8.x4.shared.b16 {%0,%1,%2,%3}, [%4];"
        : "=r"(r[0]), "=r"(r[1]), "=r"(r[2]), "=r"(r[3]) : "r"(addr));
}
__device__ __forceinline__ void mma16816(float* c, const uint32_t* a, const uint32_t* b) {
    asm volatile("mma.sync.aligned.m16n8k16.row.col.f32.bf16.bf16.f32 "
        "{%0,%1,%2,%3}, {%4,%5,%6,%7}, {%8,%9}, {%0,%1,%2,%3};"
        : "+f"(c[0]), "+f"(c[1]), "+f"(c[2]), "+f"(c[3])
        : "r"(a[0]), "r"(a[1]), "r"(a[2]), "r"(a[3]), "r"(b[0]), "r"(b[1]));
}
__device__ __forceinline__ void splitbf(float x, __nv_bfloat16& h, __nv_bfloat16& l) {
    h = __float2bfloat16(x);
    l = __float2bfloat16(x - __bfloat162float(h));
}
__device__ __forceinline__ uint32_t pk2(__nv_bfloat16 a, __nv_bfloat16 b) {
    __nv_bfloat162 t = __halves2bfloat162(a, b);
    return *(uint32_t*)&t;
}

// ================= device scratch =================
__device__ float g_M[CH_ * CH_];
__device__ float g_proc[ROWS_ * EE_];
__device__ float g_cn[ROWS_ * EE_];
__device__ float g_res2[ROWS_ * EE_];
__device__ float g_part[8 * ROWS_ * EE_];
__device__ __align__(16) __nv_bfloat16 g_cn2h[ROWS_ * EE_];
__device__ __align__(16) __nv_bfloat16 g_cn2l[ROWS_ * EE_];
__device__ __align__(16) __nv_bfloat16 g_fh[ROWS_ * DFF_];
__device__ __align__(16) __nv_bfloat16 g_fl[ROWS_ * DFF_];
__device__ __align__(16) __nv_bfloat16 g_wuph[2 * DFF_ * EE_];
__device__ __align__(16) __nv_bfloat16 g_wupl[2 * DFF_ * EE_];
__device__ __align__(16) __nv_bfloat16 g_wdnh[EE_ * DFF_];
__device__ __align__(16) __nv_bfloat16 g_wdnl[EE_ * DFF_];

// ================= setup kernels =================
__global__ void k_precompute_M(const float* __restrict__ w1,
                               const float* __restrict__ w2) {
    int idx = blockIdx.x * blockDim.x + threadIdx.x;
    int t = idx >> 6, s = idx & 63;
    float acc = 0.f;
    #pragma unroll
    for (int u = 0; u < 48; u++)
        acc += w2[t * 48 + u] * w1[u * 64 + s];
    g_M[idx] = acc;
}

__global__ void k_init(const float* __restrict__ x) {
    int idx = blockIdx.x * blockDim.x + threadIdx.x;
    int b = idx >> 15, rem = idx & 32767;
    int t = rem >> 10, e = rem & 1023;
    g_proc[(b * CH_ + ST_ + t) * EE_ + e] = x[((long)b * TT_ + t) * EE_ + e];
}

__global__ void k_cvt(const float* __restrict__ src, __nv_bfloat16* __restrict__ h,
                      __nv_bfloat16* __restrict__ l) {
    int i = (blockIdx.x * blockDim.x + threadIdx.x) * 2;
    float2 v = *(const float2*)&src[i];
    __nv_bfloat16 h0, l0, h1, l1;
    splitbf(v.x, h0, l0); splitbf(v.y, h1, l1);
    *(uint32_t*)&h[i] = pk2(h0, h1);
    *(uint32_t*)&l[i] = pk2(l0, l1);
}

// ================= LN1 =================
__global__ __launch_bounds__(256) void k_ln1(const float* __restrict__ x,
                                             const float* __restrict__ w,
                                             const float* __restrict__ bia, int step) {
    int row = blockIdx.x;
    int bb = row >> 6, t = row & 63;
    int tid = threadIdx.x;
    float4 v;
    if (t < ST_) {
        v = *(const float4*)&g_proc[(bb * CH_ + ST_ + t) * EE_ + 4 * tid];
    } else {
        int gt = step * ST_ + t;
        if (gt < TT_) v = *(const float4*)&x[((long)bb * TT_ + gt) * EE_ + 4 * tid];
        else v = make_float4(0.f, 0.f, 0.f, 0.f);
    }
    float s = v.x + v.y + v.z + v.w;
    float s2 = v.x * v.x + v.y * v.y + v.z * v.z + v.w * v.w;
    __shared__ float ws[8], ws2[8];
    #pragma unroll
    for (int o = 16; o > 0; o >>= 1) {
        s += __shfl_xor_sync(0xffffffffu, s, o);
        s2 += __shfl_xor_sync(0xffffffffu, s2, o);
    }
    int warp = tid >> 5, lane = tid & 31;
    if (lane == 0) { ws[warp] = s; ws2[warp] = s2; }
    __syncthreads();
    if (tid < 32) {
        s = (lane < 8) ? ws[lane] : 0.f;
        s2 = (lane < 8) ? ws2[lane] : 0.f;
        #pragma unroll
        for (int o = 4; o > 0; o >>= 1) {
            s += __shfl_xor_sync(0xffffffffu, s, o);
            s2 += __shfl_xor_sync(0xffffffffu, s2, o);
        }
        if (lane == 0) { ws[0] = s; ws2[0] = s2; }
    }
    __syncthreads();
    float mu = ws[0] * (1.f / EE_);
    float var = ws2[0] * (1.f / EE_) - mu * mu;
    float rs = rsqrtf(var + 1e-5f);
    float4 wv = *(const float4*)&w[4 * tid];
    float4 bv = *(const float4*)&bia[4 * tid];
    float4 o;
    o.x = (v.x - mu) * rs * wv.x + bv.x;
    o.y = (v.y - mu) * rs * wv.y + bv.y;
    o.z = (v.z - mu) * rs * wv.z + bv.z;
    o.w = (v.w - mu) * rs * wv.w + bv.w;
    *(float4*)&g_cn[row * EE_ + 4 * tid] = o;
}

// ================= temporal mix + residual =================
__global__ __launch_bounds__(256) void k_fft(const float* __restrict__ x, int step) {
    __shared__ float cns[64 * 64];
    __shared__ float Ms[64 * 64];
    int bb = blockIdx.x;
    int e0 = blockIdx.y * 64;
    int tid = threadIdx.x;
    #pragma unroll
    for (int i = 0; i < 4; i++) {
        int f4 = tid + i * 256;
        int s = f4 >> 4, e = (f4 & 15) * 4;
        *(float4*)&cns[s * 64 + e] = *(const float4*)&g_cn[(bb * 64 + s) * EE_ + e0 + e];
        *(float4*)&Ms[f4 * 4] = *(const float4*)&g_M[f4 * 4];
    }
    __syncthreads();
    int e = tid & 63;
    int tg = tid >> 6;
    float cr[64];
    #pragma unroll
    for (int s = 0; s < 64; s++) cr[s] = cns[s * 64 + e];
    #pragma unroll
    for (int i = 0; i < 16; i++) {
        int t = tg * 16 + i;
        float a = 0.f;
        #pragma unroll
        for (int s4 = 0; s4 < 16; s4++) {
            float4 m = *(float4*)&Ms[t * 64 + s4 * 4];
            a += m.x * cr[4 * s4] + m.y * cr[4 * s4 + 1] + m.z * cr[4 * s4 + 2] + m.w * cr[4 * s4 + 3];
        }
        int gt = step * ST_ + t;
        float resid = (gt < TT_) ? x[((long)bb * TT_ + gt) * EE_ + e0 + e] : 0.f;
        g_res2[(bb * 64 + t) * EE_ + e0 + e] = a + resid;
    }
}

// ================= LN2 (emits bf16 hi/lo) =================
__global__ __launch_bounds__(256) void k_ln2(const float* __restrict__ w,
                                             const float* __restrict__ bia) {
    int row = blockIdx.x;
    int tid = threadIdx.x;
    float4 v = *(const float4*)&g_res2[row * EE_ + 4 * tid];
    float s = v.x + v.y + v.z + v.w;
    float s2 = v.x * v.x + v.y * v.y + v.z * v.z + v.w * v.w;
    __shared__ float ws[8], ws2[8];
    #pragma unroll
    for (int o = 16; o > 0; o >>= 1) {
        s += __shfl_xor_sync(0xffffffffu, s, o);
        s2 += __shfl_xor_sync(0xffffffffu, s2, o);
    }
    int warp = tid >> 5, lane = tid & 31;
    if (lane == 0) { ws[warp] = s; ws2[warp] = s2; }
    __syncthreads();
    if (tid < 32) {
        s = (lane < 8) ? ws[lane] : 0.f;
        s2 = (lane < 8) ? ws2[lane] : 0.f;
        #pragma unroll
        for (int o = 4; o > 0; o >>= 1) {
            s += __shfl_xor_sync(0xffffffffu, s, o);
            s2 += __shfl_xor_sync(0xffffffffu, s2, o);
        }
        if (lane == 0) { ws[0] = s; ws2[0] = s2; }
    }
    __syncthreads();
    float mu = ws[0] * (1.f / EE_);
    float var = ws2[0] * (1.f / EE_) - mu * mu;
    float rs = rsqrtf(var + 1e-5f);
    float4 wv = *(const float4*)&w[4 * tid];
    float4 bv = *(const float4*)&bia[4 * tid];
    float o0 = (v.x - mu) * rs * wv.x + bv.x;
    float o1 = (v.y - mu) * rs * wv.y + bv.y;
    float o2 = (v.z - mu) * rs * wv.z + bv.z;
    float o3 = (v.w - mu) * rs * wv.w + bv.w;
    __nv_bfloat16 h0, l0, h1, l1, h2, l2, h3, l3;
    splitbf(o0, h0, l0); splitbf(o1, h1, l1);
    splitbf(o2, h2, l2); splitbf(o3, h3, l3);
    *(uint2*)&g_cn2h[row * EE_ + 4 * tid] = make_uint2(pk2(h0, h1), pk2(h2, h3));
    *(uint2*)&g_cn2l[row * EE_ + 4 * tid] = make_uint2(pk2(l0, l1), pk2(l2, l3));
}

// ================= UP GEMM (mma.sync bf16 3x) + sin-gate ===============
// grid (2, 64): CTA = rows m0..m0+127 x 128 interleaved cols (64 gate|val
// pairs for f-cols gn0..gn0+63). 8 warps: wm = wid&1 (64 rows),
// wn = wid>>1 (32 interleaved cols).
__global__ __launch_bounds__(256) void k_up(const float* __restrict__ b_up) {
    extern __shared__ char smem[];
    uint32_t sb = smem_u32(smem);
    int tid = threadIdx.x, wid = tid >> 5, l = tid & 31;
    int m0 = blockIdx.x * 128;
    int gn0 = blockIdx.y * 64;
    int wm = wid & 1, wn = wid >> 1;

    uint32_t aRow = (uint32_t)(wm * 64 + (l & 7) + ((l >> 3) & 1) * 8);
    uint32_t aCol = (uint32_t)(((l >> 4) & 1) * 16);
    uint32_t bRow = (uint32_t)(wn * 32 + (l & 7) + ((l >> 4) & 1) * 8);
    uint32_t bCol = (uint32_t)(((l >> 3) & 1) * 16);

    float acc[4][4][4] = {};

    // chunk loader
    auto load_chunk = [&](int c) {
        uint32_t base = sb + (uint32_t)((c & 1) * BUFSZ_);
        int k0 = c * 64;
        #pragma unroll
        for (int i = 0; i < 4; i++) {
            int idx = tid + i * 256;
            int r = idx >> 3, seg = idx & 7;
            uint32_t d0 = base + (uint32_t)(r * RS_ + seg * 16);
            cp16(d0,             &g_cn2h[(m0 + r) * EE_ + k0 + seg * 8]);
            cp16(d0 + ABUF_,     &g_cn2l[(m0 + r) * EE_ + k0 + seg * 8]);
            int wr = (r & 1) ? (DFF_ + gn0 + (r >> 1)) : (gn0 + (r >> 1));
            cp16(d0 + 2 * ABUF_, &g_wuph[(long)wr * EE_ + k0 + seg * 8]);
            cp16(d0 + 3 * ABUF_, &g_wupl[(long)wr * EE_ + k0 + seg * 8]);
        }
        CP_COMMIT();
    };
    auto compute_chunk = [&](int c) {
        uint32_t ab = sb + (uint32_t)((c & 1) * BUFSZ_);
        #pragma unroll
        for (int k0 = 0; k0 < 64; k0 += 16) {
            uint32_t ah[4][4], al[4][4], bh[2][4], bl[2][4];
            #pragma unroll
            for (int mt = 0; mt < 4; mt++) {
                uint32_t ao = ab + (aRow + mt * 16) * RS_ + k0 * 2 + aCol;
                ldmx4(ah[mt], ao);
                ldmx4(al[mt], ao + ABUF_);
            }
            #pragma unroll
            for (int np = 0; np < 2; np++) {
                uint32_t bo = ab + 2 * ABUF_ + (bRow + np * 16) * RS_ + k0 * 2 + bCol;
                ldmx4(bh[np], bo);
                ldmx4(bl[np], bo + ABUF_);
            }
            #pragma unroll
            for (int mt = 0; mt < 4; mt++)
                #pragma unroll
                for (int nt = 0; nt < 4; nt++)
                    mma16816(acc[mt][nt], ah[mt], &bh[nt >> 1][(nt & 1) * 2]);
            #pragma unroll
            for (int mt = 0; mt < 4; mt++)
                #pragma unroll
                for (int nt = 0; nt < 4; nt++)
                    mma16816(acc[mt][nt], ah[mt], &bl[nt >> 1][(nt & 1) * 2]);
            #pragma unroll
            for (int mt = 0; mt < 4; mt++)
                #pragma unroll
                for (int nt = 0; nt < 4; nt++)
                    mma16816(acc[mt][nt], al[mt], &bh[nt >> 1][(nt & 1) * 2]);
        }
    };

    load_chunk(0);
    for (int c = 0; c < 16; c++) {
        if (c + 1 < 16) { load_chunk(c + 1); CP_WAIT1(); }
        else CP_WAIT0();
        __syncthreads();
        compute_chunk(c);
        __syncthreads();
    }

    // epilogue: c0=gate, c1=val (even/odd cols), pair -> f, split bf16
    #pragma unroll
    for (int nt = 0; nt < 4; nt++) {
        int fcol = gn0 + wn * 16 + nt * 4 + (l & 3);
        float bg = b_up[fcol];
        float bv = b_up[DFF_ + fcol];
        #pragma unroll
        for (int mt = 0; mt < 4; mt++) {
            float* c = acc[mt][nt];
            int r0 = m0 + wm * 64 + mt * 16 + (l >> 2);
            float f0 = __sinf(c[0] + bg) * (c[1] + bv);
            float f1 = __sinf(c[2] + bg) * (c[3] + bv);
            __nv_bfloat16 h0, l0, h1, l1;
            splitbf(f0, h0, l0); splitbf(f1, h1, l1);
            g_fh[(long)r0 * DFF_ + fcol] = h0;
            g_fl[(long)r0 * DFF_ + fcol] = l0;
            g_fh[(long)(r0 + 8) * DFF_ + fcol] = h1;
            g_fl[(long)(r0 + 8) * DFF_ + fcol] = l1;
        }
    }
}

// ================= DOWN GEMM (mma.sync bf16 3x, split-K=8) ==============
// grid (2, 8, 8): CTA rows m0..m0+127 x cols n0..n0+127, K chunk kz*512.
__global__ __launch_bounds__(256) void k_dn() {
    extern __shared__ char smem[];
    uint32_t sb = smem_u32(smem);
    int tid = threadIdx.x, wid = tid >> 5, l = tid & 31;
    int m0 = blockIdx.x * 128;
    int n0 = blockIdx.y * 128;
    int kz = blockIdx.z;
    int wm = wid & 1, wn = wid >> 1;

    uint32_t aRow = (uint32_t)(wm * 64 + (l & 7) + ((l >> 3) & 1) * 8);
    uint32_t aCol = (uint32_t)(((l >> 4) & 1) * 16);
    uint32_t bRow = (uint32_t)(wn * 32 + (l & 7) + ((l >> 4) & 1) * 8);
    uint32_t bCol = (uint32_t)(((l >> 3) & 1) * 16);

    float acc[4][4][4] = {};

    auto load_chunk = [&](int c) {
        uint32_t base = sb + (uint32_t)((c & 1) * BUFSZ_);
        int k0 = kz * 512 + c * 64;
        #pragma unroll
        for (int i = 0; i < 4; i++) {
            int idx = tid + i * 256;
            int r = idx >> 3, seg = idx & 7;
            uint32_t d0 = base + (uint32_t)(r * RS_ + seg * 16);
            cp16(d0,             &g_fh[(long)(m0 + r) * DFF_ + k0 + seg * 8]);
            cp16(d0 + ABUF_,     &g_fl[(long)(m0 + r) * DFF_ + k0 + seg * 8]);
            cp16(d0 + 2 * ABUF_, &g_wdnh[(long)(n0 + r) * DFF_ + k0 + seg * 8]);
            cp16(d0 + 3 * ABUF_, &g_wdnl[(long)(n0 + r) * DFF_ + k0 + seg * 8]);
        }
        CP_COMMIT();
    };
    auto compute_chunk = [&](int c) {
        uint32_t ab = sb + (uint32_t)((c & 1) * BUFSZ_);
        #pragma unroll
        for (int k0 = 0; k0 < 64; k0 += 16) {
            uint32_t ah[4][4], al[4][4], bh[2][4], bl[2][4];
            #pragma unroll
            for (int mt = 0; mt < 4; mt++) {
                uint32_t ao = ab + (aRow + mt * 16) * RS_ + k0 * 2 + aCol;
                ldmx4(ah[mt], ao);
                ldmx4(al[mt], ao + ABUF_);
            }
            #pragma unroll
            for (int np = 0; np < 2; np++) {
                uint32_t bo = ab + 2 * ABUF_ + (bRow + np * 16) * RS_ + k0 * 2 + bCol;
                ldmx4(bh[np], bo);
                ldmx4(bl[np], bo + ABUF_);
            }
            #pragma unroll
            for (int mt = 0; mt < 4; mt++)
                #pragma unroll
                for (int nt = 0; nt < 4; nt++)
                    mma16816(acc[mt][nt], ah[mt], &bh[nt >> 1][(nt & 1) * 2]);
            #pragma unroll
            for (int mt = 0; mt < 4; mt++)
                #pragma unroll
                for (int nt = 0; nt < 4; nt++)
                    mma16816(acc[mt][nt], ah[mt], &bl[nt >> 1][(nt & 1) * 2]);
            #pragma unroll
            for (int mt = 0; mt < 4; mt++)
                #pragma unroll
                for (int nt = 0; nt < 4; nt++)
                    mma16816(acc[mt][nt], al[mt], &bh[nt >> 1][(nt & 1) * 2]);
        }
    };

    load_chunk(0);
    for (int c = 0; c < 8; c++) {
        if (c + 1 < 8) { load_chunk(c + 1); CP_WAIT1(); }
        else CP_WAIT0();
        __syncthreads();
        compute_chunk(c);
        __syncthreads();
    }

    float* dst = &g_part[(long)kz * (ROWS_ * EE_)];
    #pragma unroll
    for (int mt = 0; mt < 4; mt++)
        #pragma unroll
        for (int nt = 0; nt < 4; nt++) {
            float* c = acc[mt][nt];
            int col = n0 + wn * 32 + nt * 8 + (l & 3) * 2;
            int r0 = m0 + wm * 64 + mt * 16 + (l >> 2);
            *(float2*)&dst[(long)r0 * EE_ + col] = make_float2(c[0], c[1]);
            *(float2*)&dst[(long)(r0 + 8) * EE_ + col] = make_float2(c[2], c[3]);
        }
}

// ================= reduce: 8 partials + bias + res2 -> proc/out ==========
__global__ __launch_bounds__(256) void k_reduce(const float* __restrict__ b_down,
                                                float* __restrict__ out, int step) {
    int row = blockIdx.x;
    int bb = row >> 6, t = row & 63;
    int e = threadIdx.x * 4;
    float4 v = *(const float4*)&g_part[row * EE_ + e];
    #pragma unroll
    for (int p = 1; p < 8; p++) {
        float4 q = *(const float4*)&g_part[(long)p * ROWS_ * EE_ + row * EE_ + e];
        v.x += q.x; v.y += q.y; v.z += q.z; v.w += q.w;
    }
    float4 r2 = *(const float4*)&g_res2[row * EE_ + e];
    float4 bd = *(const float4*)&b_down[e];
    v.x += r2.x + bd.x; v.y += r2.y + bd.y;
    v.z += r2.z + bd.z; v.w += r2.w + bd.w;
    *(float4*)&g_proc[row * EE_ + e] = v;
    if (t < ST_)
        *(float4*)&out[((long)bb * TT_ + step * ST_ + t) * EE_ + e] = v;
}

// ================= launch =================
extern "C" void kernel_launch(void* const* d_in, const int* in_sizes, int n_in,
                              void* d_out, int out_size) {
    (void)in_sizes; (void)n_in; (void)out_size;
    const float* x      = (const float*)d_in[0];
    const float* ln1_w  = (const float*)d_in[1];
    const float* ln1_b  = (const float*)d_in[2];
    const float* w_fft1 = (const float*)d_in[3];
    const float* w_fft2 = (const float*)d_in[4];
    const float* ln2_w  = (const float*)d_in[5];
    const float* ln2_b  = (const float*)d_in[6];
    const float* w_up   = (const float*)d_in[7];
    const float* b_up   = (const float*)d_in[8];
    const float* w_down = (const float*)d_in[9];
    const float* b_down = (const float*)d_in[10];
    float* out = (float*)d_out;

    cudaFuncSetAttribute(k_up, cudaFuncAttributeMaxDynamicSharedMemorySize, GSMEM_);
    cudaFuncSetAttribute(k_dn, cudaFuncAttributeMaxDynamicSharedMemorySize, GSMEM_);

    __nv_bfloat16 *wuph, *wupl, *wdnh, *wdnl;
    cudaGetSymbolAddress((void**)&wuph, g_wuph);
    cudaGetSymbolAddress((void**)&wupl, g_wupl);
    cudaGetSymbolAddress((void**)&wdnh, g_wdnh);
    cudaGetSymbolAddress((void**)&wdnl, g_wdnl);
    k_cvt<<<(2 * DFF_ * EE_) / 512, 256>>>(w_up, wuph, wupl);
    k_cvt<<<(EE_ * DFF_) / 512, 256>>>(w_down, wdnh, wdnl);
    k_precompute_M<<<16, 256>>>(w_fft1, w_fft2);
    k_init<<<512, 256>>>(x);

    for (int i = 0; i < NCHUNK; i++) {
        k_ln1<<<ROWS_, 256>>>(x, ln1_w, ln1_b, i);
        k_fft<<<dim3(BB_, 16), 256>>>(x, i);
        k_ln2<<<ROWS_, 256>>>(ln2_w, ln2_b);
        k_up<<<dim3(2, 64), 256, GSMEM_>>>(b_up);
        k_dn<<<dim3(2, 8, 8), 256, GSMEM_>>>();
        k_reduce<<<ROWS_, 256>>>(b_down, out, i);
    }
}